// round 8
// baseline (speedup 1.0000x reference)
#include <cuda_runtime.h>
#include <cuda_bf16.h>
#include <cstdint>

// VQLayer forward == identity copy of `inputs`.
//   quantized = closest + stop_gradient(inputs - closest) == inputs (forward
//   value; stop_gradient is identity in the forward pass). rel_err 1.1e-8.
//
// R1-R4 record: 6.59 / 6.66 / 6.88 / 6.88 us across four mechanically distinct
// implementations (2048-blk LDG.128, 512-blk MLP4, driver memcpy node, default
// -cache 2048-blk) -- all within noise while no pipe exceeds 18%. Wall clock is
// a short-burst memory-system + replay floor, not a kernel property.
//
// R5: last untested lever -- Blackwell-only 256-bit global accesses
// (ld/st.global.v8.b32). Halves LSU issues and L1TEX requests per byte vs
// LDG.128. 1024 blocks x 256 threads x 32 B = 8 MB exactly.

__global__ void __launch_bounds__(256)
vq_copy_v8_kernel(const float* __restrict__ in, float* __restrict__ out) {
    size_t base = ((size_t)blockIdx.x * 256 + threadIdx.x) * 8;  // 8 floats = 32 B
    const float* src = in + base;
    float* dst = out + base;
    uint32_t r0, r1, r2, r3, r4, r5, r6, r7;
    asm volatile(
        "ld.global.nc.v8.b32 {%0,%1,%2,%3,%4,%5,%6,%7}, [%8];"
        : "=r"(r0), "=r"(r1), "=r"(r2), "=r"(r3),
          "=r"(r4), "=r"(r5), "=r"(r6), "=r"(r7)
        : "l"(src));
    asm volatile(
        "st.global.v8.b32 [%0], {%1,%2,%3,%4,%5,%6,%7,%8};"
        :: "l"(dst),
           "r"(r0), "r"(r1), "r"(r2), "r"(r3),
           "r"(r4), "r"(r5), "r"(r6), "r"(r7)
        : "memory");
}

// Fallback for sizes not divisible by 8 KB per block (not expected here).
__global__ void vq_copy_gs_kernel(const float4* __restrict__ in,
                                  float4* __restrict__ out, int n4) {
    int i = blockIdx.x * blockDim.x + threadIdx.x;
    for (; i < n4; i += gridDim.x * blockDim.x)
        out[i] = in[i];
}

extern "C" void kernel_launch(void* const* d_in, const int* in_sizes, int n_in,
                              void* d_out, int out_size) {
    // d_in[0]: inputs [32,32,32,64] float32 (2097152 elements). d_in[1]: codebook (unused).
    const int elems_per_block = 256 * 8;  // 2048 floats / block
    if (out_size % elems_per_block == 0) {
        int grid = out_size / elems_per_block;  // 1024 blocks expected
        vq_copy_v8_kernel<<<grid, 256>>>((const float*)d_in[0], (float*)d_out);
    } else {
        int n4 = out_size / 4;
        vq_copy_gs_kernel<<<(n4 + 255) / 256, 256>>>(
            (const float4*)d_in[0], (float4*)d_out, n4);
    }
}